// round 10
// baseline (speedup 1.0000x reference)
#include <cuda_runtime.h>
#include <cstdint>
#include <cstddef>

// ---------------------------------------------------------------------------
// HeteroResonance: out = (0.7*decay + 0.3*softmax(mask(q k^T / 16))) @ hdc
// B=4, T=4096, D=2048, BOT=256
// R10: legacy mma.sync tf32 (plain sm_103 PTX target -- no tcgen05).
// k-permuted operand layouts (pi(e)=(e%4)*4+e/4 within 16-groups) so all
// fragment loads are LDS.128 (16 per warp per k-tile instead of 128 LDS.32).
// Single __syncthreads per k-tile. Unified 128x256 tile, 64x64 warp tiles,
// 3-stage cp.async, n-major B everywhere (hdc^T scratch for the final GEMM).
// ---------------------------------------------------------------------------

namespace {
constexpr int kB   = 4;
constexpr int kT   = 4096;
constexpr int kD   = 2048;
constexpr int kBot = 256;
constexpr int kM1  = kB * kT;

constexpr int TM = 128;      // CTA tile M
constexpr int TN = 256;      // CTA tile N
constexpr int TK = 16;       // k-tile
constexpr int NS = 3;        // pipeline stages

constexpr int A_SZ = TM * TK;            // 2048 floats (no pad; 64B rows)
constexpr int B_SZ = TN * TK;            // 4096 floats
constexpr int STG  = A_SZ + B_SZ;        // 6144 floats = 24 KB
constexpr int SMEM = NS * STG * 4;       // 73728 B
}

// Scratch (static device globals -- allocation-free per harness rules).
// All "_r" buffers are tf32-rounded AND k-permuted within 16-groups.
__device__ __align__(256) float g_hdc_r[(size_t)kB * kT * kD];  // perm in D
__device__ __align__(256) float g_hdcT[(size_t)kB * kD * kT];   // perm in T
__device__ __align__(256) float g_wq_r[(size_t)kBot * kD];      // perm in D
__device__ __align__(256) float g_wk_r[(size_t)kBot * kD];      // perm in D
__device__ __align__(256) float g_q[(size_t)kM1 * kBot];        // perm in BOT
__device__ __align__(256) float g_k[(size_t)kM1 * kBot];        // perm in BOT
__device__ __align__(256) float g_s[(size_t)kB * kT * kT];      // perm in S

// ---------------------------------------------------------------------------
// helpers
// ---------------------------------------------------------------------------
__device__ __host__ __forceinline__ int perm16(int e) {  // involution on 0..15
    return ((e & 3) << 2) | (e >> 2);
}
__device__ __forceinline__ uint32_t f2tf(float x) {
    uint32_t r;
    asm("cvt.rna.tf32.f32 %0, %1;" : "=r"(r) : "f"(x));
    return r;
}
__device__ __forceinline__ float tfround(float x) { return __uint_as_float(f2tf(x)); }

__device__ __forceinline__ void cpa16(uint32_t saddr, const void* gaddr) {
    asm volatile("cp.async.cg.shared.global [%0], [%1], 16;" :: "r"(saddr), "l"(gaddr));
}
__device__ __forceinline__ void cp_commit() { asm volatile("cp.async.commit_group;"); }
template <int N>
__device__ __forceinline__ void cp_waitg() { asm volatile("cp.async.wait_group %0;" :: "n"(N)); }

__device__ __forceinline__ void mma8f(float c[4], float a0, float a1, float a2, float a3,
                                      float b0, float b1) {
    asm volatile(
        "mma.sync.aligned.m16n8k8.row.col.f32.tf32.tf32.f32 "
        "{%0,%1,%2,%3},{%4,%5,%6,%7},{%8,%9},{%0,%1,%2,%3};"
        : "+f"(c[0]), "+f"(c[1]), "+f"(c[2]), "+f"(c[3])
        : "r"(__float_as_uint(a0)), "r"(__float_as_uint(a1)),
          "r"(__float_as_uint(a2)), "r"(__float_as_uint(a3)),
          "r"(__float_as_uint(b0)), "r"(__float_as_uint(b1)));
}

// ---------------------------------------------------------------------------
// K0: round fp32 -> tf32 (rna) and permute within 16-groups of the
// contiguous (k) dim. which: 0=hdc, 1=Wq, 2=Wk
// ---------------------------------------------------------------------------
__global__ void k_round(const float* __restrict__ src, int n, int which) {
    float* dst = (which == 0) ? g_hdc_r : (which == 1) ? g_wq_r : g_wk_r;
    int i = blockIdx.x * blockDim.x + threadIdx.x;
    int stride = gridDim.x * blockDim.x;
    for (; i < n; i += stride) {
        int base = i & ~15, e = i & 15;
        dst[base + perm16(e)] = tfround(src[i]);
    }
}

// ---------------------------------------------------------------------------
// K0b: hdc [B][T][D] -> g_hdcT [B][D][T], tf32-rounded, permuted in T.
// ---------------------------------------------------------------------------
__global__ void k_trans(const float* __restrict__ src) {
    __shared__ float tile[32][33];
    const int bz = blockIdx.z;
    const int t0 = blockIdx.y * 32, d0 = blockIdx.x * 32;
    const float* S = src + (size_t)bz * kT * kD;
    float* Dst = g_hdcT + (size_t)bz * (size_t)kD * kT;
    const int x = threadIdx.x, y = threadIdx.y;  // 32 x 8
#pragma unroll
    for (int i = 0; i < 32; i += 8)
        tile[y + i][x] = S[(size_t)(t0 + y + i) * kD + d0 + x];
    __syncthreads();
    const int xs = (x & 16) | perm16(x & 15);    // permuted t within 32-block
#pragma unroll
    for (int i = 0; i < 32; i += 8)
        Dst[(size_t)(d0 + y + i) * kT + t0 + xs] = tfround(tile[x][y + i]);
}

// ---------------------------------------------------------------------------
// Unified tf32 GEMM: CTA 128x256, warp 64x64 (2x4 warps), 3-stage cp.async,
// one __syncthreads per k-tile, LDS.128 fragment loads (k-permuted layout).
// MODE 0: proj   C = A @ W^T + bias (tfround, perm-stored n). A=g_hdc_r.
// MODE 1: scores C = exp(mask(A@B^T/16)) (perm-stored n). A=g_q, B=g_k.
// MODE 2: out    C = A @ B^T.  A=g_s, B=g_hdcT. Plain stores.
// B is n-major (rows = n, cols = k) in all modes.
// ---------------------------------------------------------------------------
template <int MODE>
__global__ __launch_bounds__(256)
void k_gemm(const float* __restrict__ bias, float* __restrict__ outp, int which) {
    extern __shared__ float sm[];
    const int bz = blockIdx.z;
    const int m0 = blockIdx.y * TM, n0 = blockIdx.x * TN;
    const int tid = threadIdx.x;
    const int lane = tid & 31, warp = tid >> 5;
    const int g = lane >> 2, t = lane & 3;
    const int wm = warp >> 2, wn = warp & 3;    // 2 x 4 warps; warp tile 64x64

    const float* A;
    const float* Bm;
    float* C;
    int Kdim, lda, ldb, ldc;
    if (MODE == 0) {
        A   = g_hdc_r;                          lda = kD;
        Bm  = which ? g_wk_r : g_wq_r;          ldb = kD;
        C   = which ? g_k : g_q;                ldc = kBot;
        Kdim = kD;
    } else if (MODE == 1) {
        A   = g_q + (size_t)bz * kT * kBot;     lda = kBot;
        Bm  = g_k + (size_t)bz * kT * kBot;     ldb = kBot;
        C   = g_s + (size_t)bz * kT * kT;       ldc = kT;
        Kdim = kBot;
    } else {
        A   = g_s + (size_t)bz * kT * kT;       lda = kT;
        Bm  = g_hdcT + (size_t)bz * (size_t)kD * kT; ldb = kT;
        C   = outp + (size_t)bz * kT * kD;      ldc = kD;
        Kdim = kT;
    }

    // Fully-masked scores tile: store zeros, skip compute.
    if (MODE == 1 && n0 >= m0 + 124) {
        for (int i = tid * 4; i < TM * TN; i += 256 * 4) {
            int r = i / TN, c = i % TN;
            *reinterpret_cast<float4*>(&C[(size_t)(m0 + r) * ldc + n0 + c]) =
                make_float4(0.f, 0.f, 0.f, 0.f);
        }
        return;
    }

    const uint32_t sbase = (uint32_t)__cvta_generic_to_shared(sm);

    float acc[4][8][4];
#pragma unroll
    for (int a = 0; a < 4; a++)
#pragma unroll
        for (int b = 0; b < 8; b++)
#pragma unroll
            for (int c = 0; c < 4; c++) acc[a][b][c] = 0.f;

    auto load_tile = [&](int L, int s) {
        const int k0 = L * TK;
        const uint32_t aoff = sbase + (uint32_t)(s * STG) * 4u;
        const uint32_t boff = aoff + (uint32_t)A_SZ * 4u;
        // A: 128 rows x 16k = 512 chunks of 16B, 2 per thread
#pragma unroll
        for (int i = 0; i < 2; ++i) {
            int id = tid + i * 256;
            int r = id >> 2, c = (id & 3) << 2;
            cpa16(aoff + (uint32_t)(r * TK + c) * 4u,
                  A + (size_t)(m0 + r) * lda + k0 + c);
        }
        // B: 256 rows x 16k = 1024 chunks, 4 per thread
#pragma unroll
        for (int i = 0; i < 4; ++i) {
            int id = tid + i * 256;
            int r = id >> 2, c = (id & 3) << 2;
            cpa16(boff + (uint32_t)(r * TK + c) * 4u,
                  Bm + (size_t)(n0 + r) * ldb + k0 + c);
        }
        cp_commit();
    };

    const int nt = Kdim / TK;
    load_tile(0, 0);
    load_tile(1, 1);

    for (int tk = 0; tk < nt; ++tk) {
        const int s = tk % NS;
        if (tk + NS - 1 < nt) cp_waitg<NS - 2>(); else cp_waitg<0>();
        __syncthreads();   // all warps done with the buffer we now overwrite
        if (tk + NS - 1 < nt) load_tile(tk + NS - 1, (tk + NS - 1) % NS);

        const float4* At4 = reinterpret_cast<const float4*>(sm + s * STG);
        const float4* Bt4 = reinterpret_cast<const float4*>(sm + s * STG + A_SZ);

        // LDS.128 fragment loads; permuted layout => each float4 holds
        // original cols {t, t+4, t+8, t+12} = (a0/a2 | b0/b1) for both k-steps.
        float4 alo[4], ahi[4], bb[8];
#pragma unroll
        for (int mi = 0; mi < 4; ++mi) {
            int rb = wm * 64 + mi * 16;
            alo[mi] = At4[(rb + g) * 4 + t];
            ahi[mi] = At4[(rb + g + 8) * 4 + t];
        }
#pragma unroll
        for (int ni = 0; ni < 8; ++ni) {
            int cb = wn * 64 + ni * 8 + g;
            bb[ni] = Bt4[cb * 4 + t];
        }
#pragma unroll
        for (int mi = 0; mi < 4; ++mi)
#pragma unroll
            for (int ni = 0; ni < 8; ++ni) {
                mma8f(acc[mi][ni], alo[mi].x, ahi[mi].x, alo[mi].y, ahi[mi].y,
                      bb[ni].x, bb[ni].y);
                mma8f(acc[mi][ni], alo[mi].z, ahi[mi].z, alo[mi].w, ahi[mi].w,
                      bb[ni].z, bb[ni].w);
            }
        // no trailing sync: next iteration's sync protects buffer reuse
    }

    // epilogue
#pragma unroll
    for (int mi = 0; mi < 4; ++mi) {
        const int r0 = m0 + wm * 64 + mi * 16 + g;
#pragma unroll
        for (int ni = 0; ni < 8; ++ni) {
            const int col = n0 + wn * 64 + ni * 8 + 2 * t;
#pragma unroll
            for (int h = 0; h < 2; ++h) {
                const int row = r0 + h * 8;
                float v0 = acc[mi][ni][h * 2 + 0];
                float v1 = acc[mi][ni][h * 2 + 1];
                if (MODE == 2) {
                    *reinterpret_cast<float2*>(&C[(size_t)row * ldc + col]) =
                        make_float2(v0, v1);
                } else {
                    // output n becomes a downstream k: store at pi positions
                    const int pc0 = (col & ~15) | perm16(col & 15);
                    const int pc1 = ((col + 1) & ~15) | perm16((col + 1) & 15);
                    float o0, o1;
                    if (MODE == 0) {
                        o0 = tfround(v0 + bias[col]);
                        o1 = tfround(v1 + bias[col + 1]);
                    } else {
                        o0 = (col     <= row - 4) ? __expf(v0 * 0.0625f) : 0.f;
                        o1 = (col + 1 <= row - 4) ? __expf(v1 * 0.0625f) : 0.f;
                    }
                    C[(size_t)row * ldc + pc0] = o0;
                    C[(size_t)row * ldc + pc1] = o1;
                }
            }
        }
    }
}

// ---------------------------------------------------------------------------
// K3: per row of g_s (pi-permuted positions): l = sum p (perm-invariant);
// combined[x] = 0.7*decay[pi(x)] + 0.3*p[x]/l  (l==0 -> uniform 1/T),
// tf32-rounded in-place. Position x holds s-index pi(x) within its 16-group.
// ---------------------------------------------------------------------------
__global__ __launch_bounds__(256)
void k_combine(const float* __restrict__ decay) {
    __shared__ float sp[kT];
    __shared__ float red[256];
    const int r  = blockIdx.x;
    const int bz = r >> 12;
    const int i  = r & (kT - 1);
    float*       srow = g_s   + (size_t)bz * kT * kT + (size_t)i * kT;
    const float* drow = decay + (size_t)bz * kT * kT + (size_t)i * kT;
    const int tid = threadIdx.x;

    float lsum = 0.f;
    for (int j = tid * 4; j < kT; j += 1024) {
        float4 v = *reinterpret_cast<const float4*>(srow + j);
        *reinterpret_cast<float4*>(sp + j) = v;
        lsum += v.x + v.y + v.z + v.w;
    }
    red[tid] = lsum;
    __syncthreads();
    for (int s = 128; s > 0; s >>= 1) {
        if (tid < s) red[tid] += red[tid + s];
        __syncthreads();
    }
    const float l    = red[0];
    const float invl = (l > 0.f) ? (0.3f / l) : 0.f;
    const float base = (l > 0.f) ? 0.f : (0.3f / (float)kT);

    for (int x = tid * 4; x < kT; x += 1024) {
        const int g16 = x & ~15;
        const int c   = (x & 15) >> 2;       // position x+j holds s = g16+4j+c
        float d0 = drow[g16 + c];
        float d1 = drow[g16 + 4 + c];
        float d2 = drow[g16 + 8 + c];
        float d3 = drow[g16 + 12 + c];
        float4 p = *reinterpret_cast<const float4*>(sp + x);
        float4 o;
        o.x = tfround(0.7f * d0 + invl * p.x + base);
        o.y = tfround(0.7f * d1 + invl * p.y + base);
        o.z = tfround(0.7f * d2 + invl * p.z + base);
        o.w = tfround(0.7f * d3 + invl * p.w + base);
        *reinterpret_cast<float4*>(srow + x) = o;
    }
}

// ---------------------------------------------------------------------------
// launch
// ---------------------------------------------------------------------------
extern "C" void kernel_launch(void* const* d_in, const int* in_sizes, int n_in,
                              void* d_out, int out_size) {
    (void)in_sizes; (void)n_in; (void)out_size;
    const float* hdc   = (const float*)d_in[0];
    const float* decay = (const float*)d_in[1];
    const float* Wq    = (const float*)d_in[2];
    const float* bq    = (const float*)d_in[3];
    const float* Wk    = (const float*)d_in[4];
    const float* bk    = (const float*)d_in[5];
    float* out = (float*)d_out;

    static bool attr_done = false;
    if (!attr_done) {
        cudaFuncSetAttribute(k_gemm<0>, cudaFuncAttributeMaxDynamicSharedMemorySize, SMEM);
        cudaFuncSetAttribute(k_gemm<1>, cudaFuncAttributeMaxDynamicSharedMemorySize, SMEM);
        cudaFuncSetAttribute(k_gemm<2>, cudaFuncAttributeMaxDynamicSharedMemorySize, SMEM);
        attr_done = true;
    }

    k_round<<<8192, 256>>>(hdc, kB * kT * kD, 0);
    k_round<<<512, 256>>>(Wq, kBot * kD, 1);
    k_round<<<512, 256>>>(Wk, kBot * kD, 2);
    k_trans<<<dim3(kD / 32, kT / 32, kB), dim3(32, 8)>>>(hdc);

    // projections: C[16384,256] = hdc @ W^T + b
    k_gemm<0><<<dim3(kBot / TN, kM1 / TM, 1), 256, SMEM>>>(bq, nullptr, 0);
    k_gemm<0><<<dim3(kBot / TN, kM1 / TM, 1), 256, SMEM>>>(bk, nullptr, 1);

    // scores -> p
    k_gemm<1><<<dim3(kT / TN, kT / TM, kB), 256, SMEM>>>(nullptr, nullptr, 0);

    k_combine<<<kM1, 256>>>(decay);

    // out = combined @ hdc
    k_gemm<2><<<dim3(kD / TN, kT / TM, kB), 256, SMEM>>>(nullptr, out, 0);
}

// round 12
// speedup vs baseline: 1.7215x; 1.7215x over previous
#include <cuda_runtime.h>
#include <cuda_fp16.h>
#include <cstdint>
#include <cstddef>

// ---------------------------------------------------------------------------
// HeteroResonance: out = (0.7*decay + 0.3*softmax(mask(q k^T / 16))) @ hdc
// B=4, T=4096, D=2048, BOT=256
// R11: all GEMMs on fp16 mma.sync m16n8k16 with fp32 accumulation.
// fp16 significand (11 bits) == tf32 significand -> same accuracy, 2x rate,
// 2x K per instruction. Softmax stored as exp(score-6) (shift-invariant) to
// keep fp16 storage safely in range. k-permuted operand layout (32-groups)
// so fragments for both k-steps load as single LDS.128.
// ---------------------------------------------------------------------------

namespace {
constexpr int kB   = 4;
constexpr int kT   = 4096;
constexpr int kD   = 2048;
constexpr int kBot = 256;
constexpr int kM1  = kB * kT;

constexpr int TM = 128;      // CTA tile M
constexpr int TN = 256;      // CTA tile N
constexpr int TK = 32;       // k-tile (halfs) = 64 B/row
constexpr int NS = 3;        // pipeline stages

constexpr int A_HALFS = TM * TK;                 // 4096
constexpr int B_HALFS = TN * TK;                 // 8192
constexpr int STG_B   = (A_HALFS + B_HALFS) * 2; // 24576 bytes per stage
constexpr int SMEM    = NS * STG_B;              // 73728 B
}

// Scratch (static device globals -- allocation-free per harness rules).
// All half buffers are fp16-rounded AND k-permuted within 32-groups.
__device__ __align__(256) __half g_hdc_h[(size_t)kB * kT * kD];  // perm in D
__device__ __align__(256) __half g_hdcT[(size_t)kB * kD * kT];   // perm in T
__device__ __align__(256) __half g_wq_h[(size_t)kBot * kD];      // perm in D
__device__ __align__(256) __half g_wk_h[(size_t)kBot * kD];      // perm in D
__device__ __align__(256) __half g_q[(size_t)kM1 * kBot];        // perm in BOT
__device__ __align__(256) __half g_k[(size_t)kM1 * kBot];        // perm in BOT
__device__ __align__(256) __half g_s[(size_t)kB * kT * kT];      // perm in S

// ---------------------------------------------------------------------------
// k-permutation within 32-groups. Position p holds original element orig32(p).
// Chunk t (halfs 8t..8t+7) = {2t,2t+1,2t+8,2t+9, 16+2t,16+2t+1,16+2t+8,16+2t+9}
// => thread t's LDS.128 yields mma fragments for both k-steps of a 32-k tile.
// ---------------------------------------------------------------------------
__device__ __forceinline__ int orig32(int p) {
    int t = p >> 3, j = p & 7;
    int base = (j & 4) << 2;           // 0 or 16
    int jj = j & 3;
    return base + 2 * t + (jj & 1) + ((jj & 2) ? 8 : 0);
}
__device__ __forceinline__ int inv32(int o) {
    int b16 = (o >> 4) & 1, r = o & 15;
    int t = (r >> 1) & 3, lsb = r & 1, hi8 = (r >> 3) & 1;
    return 8 * t + (b16 << 2) + (hi8 << 1) + lsb;
}

__device__ __forceinline__ void cpa16(uint32_t saddr, const void* gaddr) {
    asm volatile("cp.async.cg.shared.global [%0], [%1], 16;" :: "r"(saddr), "l"(gaddr));
}
__device__ __forceinline__ void cp_commit() { asm volatile("cp.async.commit_group;"); }
template <int N>
__device__ __forceinline__ void cp_waitg() { asm volatile("cp.async.wait_group %0;" :: "n"(N)); }

__device__ __forceinline__ void mma16(float c[4], uint32_t a0, uint32_t a1,
                                      uint32_t a2, uint32_t a3,
                                      uint32_t b0, uint32_t b1) {
    asm volatile(
        "mma.sync.aligned.m16n8k16.row.col.f32.f16.f16.f32 "
        "{%0,%1,%2,%3},{%4,%5,%6,%7},{%8,%9},{%0,%1,%2,%3};"
        : "+f"(c[0]), "+f"(c[1]), "+f"(c[2]), "+f"(c[3])
        : "r"(a0), "r"(a1), "r"(a2), "r"(a3), "r"(b0), "r"(b1));
}

// ---------------------------------------------------------------------------
// K0: fp32 -> fp16 (rn) with 32-group k-permutation. which: 0=hdc, 1=Wq, 2=Wk
// ---------------------------------------------------------------------------
__global__ void k_toh(const float* __restrict__ src, int n, int which) {
    __half* dst = (which == 0) ? g_hdc_h : (which == 1) ? g_wq_h : g_wk_h;
    int i = blockIdx.x * blockDim.x + threadIdx.x;
    int stride = gridDim.x * blockDim.x;
    for (; i < n; i += stride)
        dst[i] = __float2half_rn(src[(i & ~31) + orig32(i & 31)]);
}

// ---------------------------------------------------------------------------
// K0b: hdc [B][T][D] -> g_hdcT [B][D][T] fp16, permuted in T (32-groups).
// ---------------------------------------------------------------------------
__global__ void k_trans(const float* __restrict__ src) {
    __shared__ float tile[32][33];
    const int bz = blockIdx.z;
    const int t0 = blockIdx.y * 32, d0 = blockIdx.x * 32;
    const float* S = src + (size_t)bz * kT * kD;
    __half* Dst = g_hdcT + (size_t)bz * (size_t)kD * kT;
    const int x = threadIdx.x, y = threadIdx.y;  // 32 x 8
#pragma unroll
    for (int i = 0; i < 32; i += 8)
        tile[y + i][x] = S[(size_t)(t0 + y + i) * kD + d0 + x];
    __syncthreads();
    const int xo = orig32(x);
#pragma unroll
    for (int i = 0; i < 32; i += 8)
        Dst[(size_t)(d0 + y + i) * kT + t0 + x] = __float2half_rn(tile[xo][y + i]);
}

// ---------------------------------------------------------------------------
// Unified fp16 GEMM: CTA 128x256, warp 64x64 (2x4 warps), 3-stage cp.async,
// one __syncthreads per k-tile, LDS.128 fragments (permuted layout).
// MODE 0: proj   q/k = hdc @ W^T + bias   (half out, perm-stored n)
// MODE 1: scores p' = exp(mask(A@B^T)/16 - 6)  (half out, perm-stored n)
// MODE 2: out    C = combined @ hdc       (fp32 out, plain)
// B operand is n-major (rows = n, cols = k) in all modes.
// ---------------------------------------------------------------------------
template <int MODE>
__global__ __launch_bounds__(256)
void k_gemm(const float* __restrict__ bias, float* __restrict__ outp, int which) {
    extern __shared__ __half smh[];
    const int bz = blockIdx.z;
    const int m0 = blockIdx.y * TM, n0 = blockIdx.x * TN;
    const int tid = threadIdx.x;
    const int lane = tid & 31, warp = tid >> 5;
    const int g = lane >> 2, t = lane & 3;
    const int wm = warp >> 2, wn = warp & 3;    // 2 x 4 warps; warp tile 64x64

    const __half* A;
    const __half* Bm;
    __half* Ch = nullptr;
    float*  Cf = nullptr;
    int Kdim, lda, ldb, ldc;
    if (MODE == 0) {
        A   = g_hdc_h;                          lda = kD;
        Bm  = which ? g_wk_h : g_wq_h;          ldb = kD;
        Ch  = which ? g_k : g_q;                ldc = kBot;
        Kdim = kD;
    } else if (MODE == 1) {
        A   = g_q + (size_t)bz * kT * kBot;     lda = kBot;
        Bm  = g_k + (size_t)bz * kT * kBot;     ldb = kBot;
        Ch  = g_s + (size_t)bz * kT * kT;       ldc = kT;
        Kdim = kBot;
    } else {
        A   = g_s + (size_t)bz * kT * kT;       lda = kT;
        Bm  = g_hdcT + (size_t)bz * (size_t)kD * kT; ldb = kT;
        Cf  = outp + (size_t)bz * kT * kD;      ldc = kD;
        Kdim = kT;
    }

    // Fully-masked scores tile: store zeros, skip compute.
    if (MODE == 1 && n0 >= m0 + 124) {
        uint4 z = make_uint4(0, 0, 0, 0);
        for (int i = tid * 8; i < TM * TN; i += 256 * 8) {
            int r = i / TN, c = i % TN;
            *reinterpret_cast<uint4*>(&Ch[(size_t)(m0 + r) * ldc + n0 + c]) = z;
        }
        return;
    }

    const uint32_t sbase = (uint32_t)__cvta_generic_to_shared(smh);

    float acc[4][8][4];
#pragma unroll
    for (int a = 0; a < 4; a++)
#pragma unroll
        for (int b = 0; b < 8; b++)
#pragma unroll
            for (int c = 0; c < 4; c++) acc[a][b][c] = 0.f;

    auto load_tile = [&](int L, int s) {
        const int k0 = L * TK;
        const uint32_t aoff = sbase + (uint32_t)(s * STG_B);
        const uint32_t boff = aoff + (uint32_t)(A_HALFS * 2);
        // A: 128 rows x 4 chunks(16B) = 512 chunks, 2 per thread
#pragma unroll
        for (int i = 0; i < 2; ++i) {
            int id = tid + i * 256;
            int r = id >> 2, c = id & 3;
            cpa16(aoff + (uint32_t)(r * 64 + c * 16),
                  A + (size_t)(m0 + r) * lda + k0 + c * 8);
        }
        // B: 256 rows x 4 chunks = 1024 chunks, 4 per thread
#pragma unroll
        for (int i = 0; i < 4; ++i) {
            int id = tid + i * 256;
            int r = id >> 2, c = id & 3;
            cpa16(boff + (uint32_t)(r * 64 + c * 16),
                  Bm + (size_t)(n0 + r) * ldb + k0 + c * 8);
        }
        cp_commit();
    };

    const int nt = Kdim / TK;
    load_tile(0, 0);
    load_tile(1, 1);

    for (int tk = 0; tk < nt; ++tk) {
        const int s = tk % NS;
        if (tk + NS - 1 < nt) cp_waitg<NS - 2>(); else cp_waitg<0>();
        __syncthreads();   // all warps done with the buffer we now overwrite
        if (tk + NS - 1 < nt) load_tile(tk + NS - 1, (tk + NS - 1) % NS);

        const uint4* At4 = reinterpret_cast<const uint4*>(
            reinterpret_cast<const char*>(smh) + s * STG_B);
        const uint4* Bt4 = reinterpret_cast<const uint4*>(
            reinterpret_cast<const char*>(smh) + s * STG_B + A_HALFS * 2);

        // LDS.128 fragments: one uint4 per row covers both k-steps.
        uint4 af0[4], af1[4], bb[8];
#pragma unroll
        for (int mi = 0; mi < 4; ++mi) {
            int rb = wm * 64 + mi * 16;
            af0[mi] = At4[(rb + g) * 4 + t];
            af1[mi] = At4[(rb + g + 8) * 4 + t];
        }
#pragma unroll
        for (int ni = 0; ni < 8; ++ni) {
            int cb = wn * 64 + ni * 8 + g;
            bb[ni] = Bt4[cb * 4 + t];
        }
        // k-step 0 (all 32 distinct accumulators), then k-step 1
#pragma unroll
        for (int mi = 0; mi < 4; ++mi)
#pragma unroll
            for (int ni = 0; ni < 8; ++ni)
                mma16(acc[mi][ni], af0[mi].x, af1[mi].x, af0[mi].y, af1[mi].y,
                      bb[ni].x, bb[ni].y);
#pragma unroll
        for (int mi = 0; mi < 4; ++mi)
#pragma unroll
            for (int ni = 0; ni < 8; ++ni)
                mma16(acc[mi][ni], af0[mi].z, af1[mi].z, af0[mi].w, af1[mi].w,
                      bb[ni].z, bb[ni].w);
        // no trailing sync: next iteration's sync protects buffer reuse
    }

    // epilogue
#pragma unroll
    for (int mi = 0; mi < 4; ++mi) {
        const int r0 = m0 + wm * 64 + mi * 16 + g;
#pragma unroll
        for (int ni = 0; ni < 8; ++ni) {
            const int col = n0 + wn * 64 + ni * 8 + 2 * t;
#pragma unroll
            for (int h = 0; h < 2; ++h) {
                const int row = r0 + h * 8;
                float v0 = acc[mi][ni][h * 2 + 0];
                float v1 = acc[mi][ni][h * 2 + 1];
                if (MODE == 2) {
                    *reinterpret_cast<float2*>(&Cf[(size_t)row * ldc + col]) =
                        make_float2(v0, v1);
                } else {
                    // output n becomes a downstream k: store at permuted pos
                    const int pc0 = (col & ~31) | inv32(col & 31);
                    const int pc1 = ((col + 1) & ~31) | inv32((col + 1) & 31);
                    __half o0, o1;
                    if (MODE == 0) {
                        o0 = __float2half_rn(v0 + bias[col]);
                        o1 = __float2half_rn(v1 + bias[col + 1]);
                    } else {
                        o0 = (col     <= row - 4)
                                 ? __float2half_rn(__expf(v0 * 0.0625f - 6.0f))
                                 : __half(0.f);
                        o1 = (col + 1 <= row - 4)
                                 ? __float2half_rn(__expf(v1 * 0.0625f - 6.0f))
                                 : __half(0.f);
                    }
                    Ch[(size_t)row * ldc + pc0] = o0;
                    Ch[(size_t)row * ldc + pc1] = o1;
                }
            }
        }
    }
}

// ---------------------------------------------------------------------------
// K3: per row of g_s (permuted positions, fp16): l = sum p' (perm-invariant);
// combined[x] = 0.7*decay[orig(x)] + 0.3*p'[x]/l  (l==0 -> uniform 1/T).
// Stored fp16 in place (A operand of the final GEMM).
// ---------------------------------------------------------------------------
__global__ __launch_bounds__(256)
void k_combine(const float* __restrict__ decay) {
    __shared__ float red[256];
    const int r  = blockIdx.x;
    const int bz = r >> 12;
    const int i  = r & (kT - 1);
    __half*      srow = g_s   + (size_t)bz * kT * kT + (size_t)i * kT;
    const float* drow = decay + (size_t)bz * kT * kT + (size_t)i * kT;
    const int tid = threadIdx.x;

    // pass 1: row sum (fp32)
    float lsum = 0.f;
#pragma unroll
    for (int it = 0; it < 2; ++it) {
        int x = (tid + it * 256) * 8;
        uint4 pv = *reinterpret_cast<const uint4*>(srow + x);
        const __half2* ph = reinterpret_cast<const __half2*>(&pv);
#pragma unroll
        for (int j = 0; j < 4; ++j) {
            float2 f = __half22float2(ph[j]);
            lsum += f.x + f.y;
        }
    }
    red[tid] = lsum;
    __syncthreads();
    for (int s = 128; s > 0; s >>= 1) {
        if (tid < s) red[tid] += red[tid + s];
        __syncthreads();
    }
    const float l    = red[0];
    const float invl = (l > 0.f) ? (0.3f / l) : 0.f;
    const float base = (l > 0.f) ? 0.f : (0.3f / (float)kT);

    // pass 2: combine. Positions x..x+7 are chunk t of a 32-group:
    // orig cols = g32 + {2t,2t+1, 2t+8,2t+9, 2t+16,2t+17, 2t+24,2t+25}.
#pragma unroll
    for (int it = 0; it < 2; ++it) {
        int x = (tid + it * 256) * 8;
        int g32 = x & ~31;
        int ct  = (x & 31) >> 3;          // chunk index 0..3
        int j0  = g32 + 2 * ct;
        float2 d0 = *reinterpret_cast<const float2*>(drow + j0);
        float2 d1 = *reinterpret_cast<const float2*>(drow + j0 + 8);
        float2 d2 = *reinterpret_cast<const float2*>(drow + j0 + 16);
        float2 d3 = *reinterpret_cast<const float2*>(drow + j0 + 24);
        uint4 pv = *reinterpret_cast<const uint4*>(srow + x);
        const __half2* ph = reinterpret_cast<const __half2*>(&pv);
        float2 p0 = __half22float2(ph[0]);
        float2 p1 = __half22float2(ph[1]);
        float2 p2 = __half22float2(ph[2]);
        float2 p3 = __half22float2(ph[3]);
        uint4 ov;
        __half2* oh = reinterpret_cast<__half2*>(&ov);
        oh[0] = __floats2half2_rn(0.7f * d0.x + invl * p0.x + base,
                                  0.7f * d0.y + invl * p0.y + base);
        oh[1] = __floats2half2_rn(0.7f * d1.x + invl * p1.x + base,
                                  0.7f * d1.y + invl * p1.y + base);
        oh[2] = __floats2half2_rn(0.7f * d2.x + invl * p2.x + base,
                                  0.7f * d2.y + invl * p2.y + base);
        oh[3] = __floats2half2_rn(0.7f * d3.x + invl * p3.x + base,
                                  0.7f * d3.y + invl * p3.y + base);
        *reinterpret_cast<uint4*>(srow + x) = ov;
    }
}

// ---------------------------------------------------------------------------
// launch
// ---------------------------------------------------------------------------
extern "C" void kernel_launch(void* const* d_in, const int* in_sizes, int n_in,
                              void* d_out, int out_size) {
    (void)in_sizes; (void)n_in; (void)out_size;
    const float* hdc   = (const float*)d_in[0];
    const float* decay = (const float*)d_in[1];
    const float* Wq    = (const float*)d_in[2];
    const float* bq    = (const float*)d_in[3];
    const float* Wk    = (const float*)d_in[4];
    const float* bk    = (const float*)d_in[5];
    float* out = (float*)d_out;

    static bool attr_done = false;
    if (!attr_done) {
        cudaFuncSetAttribute(k_gemm<0>, cudaFuncAttributeMaxDynamicSharedMemorySize, SMEM);
        cudaFuncSetAttribute(k_gemm<1>, cudaFuncAttributeMaxDynamicSharedMemorySize, SMEM);
        cudaFuncSetAttribute(k_gemm<2>, cudaFuncAttributeMaxDynamicSharedMemorySize, SMEM);
        attr_done = true;
    }

    k_toh<<<8192, 256>>>(hdc, kB * kT * kD, 0);
    k_toh<<<512, 256>>>(Wq, kBot * kD, 1);
    k_toh<<<512, 256>>>(Wk, kBot * kD, 2);
    k_trans<<<dim3(kD / 32, kT / 32, kB), dim3(32, 8)>>>(hdc);

    // projections: q/k[16384,256] = hdc @ W^T + b
    k_gemm<0><<<dim3(kBot / TN, kM1 / TM, 1), 256, SMEM>>>(bq, nullptr, 0);
    k_gemm<0><<<dim3(kBot / TN, kM1 / TM, 1), 256, SMEM>>>(bk, nullptr, 1);

    // scores -> p' = exp(score - 6)
    k_gemm<1><<<dim3(kT / TN, kT / TM, kB), 256, SMEM>>>(nullptr, nullptr, 0);

    k_combine<<<kM1, 256>>>(decay);

    // out = combined @ hdc
    k_gemm<2><<<dim3(kD / TN, kT / TM, kB), 256, SMEM>>>(nullptr, out, 0);
}

// round 17
// speedup vs baseline: 1.8632x; 1.0823x over previous
#include <cuda_runtime.h>
#include <cuda_fp16.h>
#include <cstdint>
#include <cstddef>

// ---------------------------------------------------------------------------
// HeteroResonance: out = (0.7*decay + 0.3*softmax(mask(q k^T / 16))) @ hdc
// B=4, T=4096, D=2048, BOT=256
// R14 (= R13 resubmit; infra failure last round): fp16 m16n8k16 GEMMs
// (fp32 accum).
//  - pipeline stages hold 2x32-k sub-tiles (one sync per 64 k)
//  - q & k projections fused into one launch (gridDim.z = 2)
//  - hdc fp16 convert + transpose fused (hdc read once)
// k-permuted operand layout (32-groups) -> all fragment loads are LDS.128.
// ---------------------------------------------------------------------------

namespace {
constexpr int kB   = 4;
constexpr int kT   = 4096;
constexpr int kD   = 2048;
constexpr int kBot = 256;
constexpr int kM1  = kB * kT;

constexpr int TM = 128;      // CTA tile M
constexpr int TN = 256;      // CTA tile N
constexpr int TK = 32;       // sub-tile k (halfs) = 64 B/row
constexpr int NSUB = 2;      // sub-tiles per pipeline stage (64 k per stage)
constexpr int NS = 3;        // pipeline stages

constexpr int A_HALFS = TM * TK;                 // 4096
constexpr int B_HALFS = TN * TK;                 // 8192
constexpr int SUB_B   = (A_HALFS + B_HALFS) * 2; // 24576 B per sub-tile
constexpr int STG_B   = NSUB * SUB_B;            // 49152 B per stage
constexpr int SMEM    = NS * STG_B;              // 147456 B
}

// Scratch (static device globals -- allocation-free per harness rules).
// All half buffers are fp16-rounded AND k-permuted within 32-groups.
__device__ __align__(256) __half g_hdc_h[(size_t)kB * kT * kD];  // perm in D
__device__ __align__(256) __half g_hdcT[(size_t)kB * kD * kT];   // perm in T
__device__ __align__(256) __half g_wq_h[(size_t)kBot * kD];      // perm in D
__device__ __align__(256) __half g_wk_h[(size_t)kBot * kD];      // perm in D
__device__ __align__(256) __half g_q[(size_t)kM1 * kBot];        // perm in BOT
__device__ __align__(256) __half g_k[(size_t)kM1 * kBot];        // perm in BOT
__device__ __align__(256) __half g_s[(size_t)kB * kT * kT];      // perm in S

// ---------------------------------------------------------------------------
// k-permutation within 32-groups. Position p holds original element orig32(p).
// Chunk t (halfs 8t..8t+7) = {2t,2t+1,2t+8,2t+9, 16+2t,...} so one LDS.128
// yields a thread's mma fragments for both k-steps of a 32-k sub-tile.
// ---------------------------------------------------------------------------
__device__ __forceinline__ int orig32(int p) {
    int t = p >> 3, j = p & 7;
    int base = (j & 4) << 2;           // 0 or 16
    int jj = j & 3;
    return base + 2 * t + (jj & 1) + ((jj & 2) ? 8 : 0);
}
__device__ __forceinline__ int inv32(int o) {
    int b16 = (o >> 4) & 1, r = o & 15;
    int t = (r >> 1) & 3, lsb = r & 1, hi8 = (r >> 3) & 1;
    return 8 * t + (b16 << 2) + (hi8 << 1) + lsb;
}

__device__ __forceinline__ void cpa16(uint32_t saddr, const void* gaddr) {
    asm volatile("cp.async.cg.shared.global [%0], [%1], 16;" :: "r"(saddr), "l"(gaddr));
}
__device__ __forceinline__ void cp_commit() { asm volatile("cp.async.commit_group;"); }
template <int N>
__device__ __forceinline__ void cp_waitg() { asm volatile("cp.async.wait_group %0;" :: "n"(N)); }

__device__ __forceinline__ void mma16(float c[4], uint32_t a0, uint32_t a1,
                                      uint32_t a2, uint32_t a3,
                                      uint32_t b0, uint32_t b1) {
    asm volatile(
        "mma.sync.aligned.m16n8k16.row.col.f32.f16.f16.f32 "
        "{%0,%1,%2,%3},{%4,%5,%6,%7},{%8,%9},{%0,%1,%2,%3};"
        : "+f"(c[0]), "+f"(c[1]), "+f"(c[2]), "+f"(c[3])
        : "r"(a0), "r"(a1), "r"(a2), "r"(a3), "r"(b0), "r"(b1));
}

// ---------------------------------------------------------------------------
// K0: fp32 -> fp16 (rn) with 32-group k-permutation. which: 1=Wq, 2=Wk
// ---------------------------------------------------------------------------
__global__ void k_toh(const float* __restrict__ src, int n, int which) {
    __half* dst = (which == 1) ? g_wq_h : g_wk_h;
    int i = blockIdx.x * blockDim.x + threadIdx.x;
    int stride = gridDim.x * blockDim.x;
    for (; i < n; i += stride)
        dst[i] = __float2half_rn(src[(i & ~31) + orig32(i & 31)]);
}

// ---------------------------------------------------------------------------
// K0b: read hdc once; write BOTH g_hdc_h (perm in D) and g_hdcT (perm in T).
// ---------------------------------------------------------------------------
__global__ void k_prep_hdc(const float* __restrict__ src) {
    __shared__ float tile[32][33];
    const int bz = blockIdx.z;
    const int t0 = blockIdx.y * 32, d0 = blockIdx.x * 32;
    const float* S = src + (size_t)bz * kT * kD;
    __half* Dh = g_hdc_h + (size_t)bz * kT * kD;
    __half* Dt = g_hdcT + (size_t)bz * (size_t)kD * kT;
    const int x = threadIdx.x, y = threadIdx.y;  // 32 x 8
    const int xi = inv32(x);                     // perm position for col x
#pragma unroll
    for (int i = 0; i < 32; i += 8) {
        float v = S[(size_t)(t0 + y + i) * kD + d0 + x];
        tile[y + i][x] = v;
        Dh[(size_t)(t0 + y + i) * kD + d0 + xi] = __float2half_rn(v);
    }
    __syncthreads();
    const int xo = orig32(x);
#pragma unroll
    for (int i = 0; i < 32; i += 8)
        Dt[(size_t)(d0 + y + i) * kT + t0 + x] = __float2half_rn(tile[xo][y + i]);
}

// ---------------------------------------------------------------------------
// Unified fp16 GEMM: CTA 128x256, warp 64x64 (2x4 warps), 3-stage cp.async
// (each stage = 2 sub-tiles of 32 k; one sync per 64 k), LDS.128 fragments.
// MODE 0: proj   q/k = hdc @ W^T + bias (half out, perm n). blockIdx.z=which.
// MODE 1: scores p' = exp(mask(A@B^T)/16 - 6) (half out, perm n)
// MODE 2: out    C = combined @ hdc (fp32 out, plain)
// B operand is n-major (rows = n, cols = k) in all modes.
// ---------------------------------------------------------------------------
template <int MODE>
__global__ __launch_bounds__(256)
void k_gemm(const float* __restrict__ bias, float* __restrict__ outp) {
    extern __shared__ __half smh[];
    const int bz = blockIdx.z;
    const int m0 = blockIdx.y * TM, n0 = blockIdx.x * TN;
    const int tid = threadIdx.x;
    const int lane = tid & 31, warp = tid >> 5;
    const int g = lane >> 2, t = lane & 3;
    const int wm = warp >> 2, wn = warp & 3;    // 2 x 4 warps; warp tile 64x64

    const __half* A;
    const __half* Bm;
    __half* Ch = nullptr;
    float*  Cf = nullptr;
    const float* bvec = nullptr;
    int Kdim, lda, ldb, ldc;
    if (MODE == 0) {
        A    = g_hdc_h;                          lda = kD;
        Bm   = bz ? g_wk_h : g_wq_h;             ldb = kD;
        Ch   = bz ? g_k : g_q;                   ldc = kBot;
        bvec = bz ? (const float*)outp : bias;   // bk smuggled via outp
        Kdim = kD;
    } else if (MODE == 1) {
        A   = g_q + (size_t)bz * kT * kBot;      lda = kBot;
        Bm  = g_k + (size_t)bz * kT * kBot;      ldb = kBot;
        Ch  = g_s + (size_t)bz * kT * kT;        ldc = kT;
        Kdim = kBot;
    } else {
        A   = g_s + (size_t)bz * kT * kT;        lda = kT;
        Bm  = g_hdcT + (size_t)bz * (size_t)kD * kT; ldb = kT;
        Cf  = outp + (size_t)bz * kT * kD;       ldc = kD;
        Kdim = kT;
    }

    // Fully-masked scores tile: store zeros, skip compute.
    if (MODE == 1 && n0 >= m0 + 124) {
        uint4 z = make_uint4(0, 0, 0, 0);
        for (int i = tid * 8; i < TM * TN; i += 256 * 8) {
            int r = i / TN, c = i % TN;
            *reinterpret_cast<uint4*>(&Ch[(size_t)(m0 + r) * ldc + n0 + c]) = z;
        }
        return;
    }

    const uint32_t sbase = (uint32_t)__cvta_generic_to_shared(smh);

    float acc[4][8][4];
#pragma unroll
    for (int a = 0; a < 4; a++)
#pragma unroll
        for (int b = 0; b < 8; b++)
#pragma unroll
            for (int c = 0; c < 4; c++) acc[a][b][c] = 0.f;

    // load one 64-k stage (2 sub-tiles); single commit
    auto load_stage = [&](int L, int s) {
#pragma unroll
        for (int sub = 0; sub < NSUB; ++sub) {
            const int k0 = L * (TK * NSUB) + sub * TK;
            const uint32_t aoff = sbase + (uint32_t)(s * STG_B + sub * SUB_B);
            const uint32_t boff = aoff + (uint32_t)(A_HALFS * 2);
            // A: 128 rows x 4 chunks(16B) = 512 chunks, 2 per thread
#pragma unroll
            for (int i = 0; i < 2; ++i) {
                int id = tid + i * 256;
                int r = id >> 2, c = id & 3;
                cpa16(aoff + (uint32_t)(r * 64 + c * 16),
                      A + (size_t)(m0 + r) * lda + k0 + c * 8);
            }
            // B: 256 rows x 4 chunks = 1024 chunks, 4 per thread
#pragma unroll
            for (int i = 0; i < 4; ++i) {
                int id = tid + i * 256;
                int r = id >> 2, c = id & 3;
                cpa16(boff + (uint32_t)(r * 64 + c * 16),
                      Bm + (size_t)(n0 + r) * ldb + k0 + c * 8);
            }
        }
        cp_commit();
    };

    const int nt = Kdim / (TK * NSUB);   // outer stages: proj 32, scores 4, out 64
    load_stage(0, 0);
    load_stage(1, 1);

    for (int ot = 0; ot < nt; ++ot) {
        const int s = ot % NS;
        if (ot + NS - 1 < nt) cp_waitg<NS - 2>(); else cp_waitg<0>();
        __syncthreads();   // all warps done with the buffer we now overwrite
        if (ot + NS - 1 < nt) load_stage(ot + NS - 1, (ot + NS - 1) % NS);

#pragma unroll
        for (int sub = 0; sub < NSUB; ++sub) {
            const uint4* At4 = reinterpret_cast<const uint4*>(
                reinterpret_cast<const char*>(smh) + s * STG_B + sub * SUB_B);
            const uint4* Bt4 = reinterpret_cast<const uint4*>(
                reinterpret_cast<const char*>(smh) + s * STG_B + sub * SUB_B +
                A_HALFS * 2);

            // LDS.128 fragments: one uint4 per row covers both k-steps.
            uint4 af0[4], af1[4], bb[8];
#pragma unroll
            for (int mi = 0; mi < 4; ++mi) {
                int rb = wm * 64 + mi * 16;
                af0[mi] = At4[(rb + g) * 4 + t];
                af1[mi] = At4[(rb + g + 8) * 4 + t];
            }
#pragma unroll
            for (int ni = 0; ni < 8; ++ni) {
                int cb = wn * 64 + ni * 8 + g;
                bb[ni] = Bt4[cb * 4 + t];
            }
            // k-step 0 (32 distinct accumulators), then k-step 1
#pragma unroll
            for (int mi = 0; mi < 4; ++mi)
#pragma unroll
                for (int ni = 0; ni < 8; ++ni)
                    mma16(acc[mi][ni], af0[mi].x, af1[mi].x, af0[mi].y,
                          af1[mi].y, bb[ni].x, bb[ni].y);
#pragma unroll
            for (int mi = 0; mi < 4; ++mi)
#pragma unroll
                for (int ni = 0; ni < 8; ++ni)
                    mma16(acc[mi][ni], af0[mi].z, af1[mi].z, af0[mi].w,
                          af1[mi].w, bb[ni].z, bb[ni].w);
        }
        // no trailing sync: next iteration's sync protects buffer reuse
    }

    // epilogue
#pragma unroll
    for (int mi = 0; mi < 4; ++mi) {
        const int r0 = m0 + wm * 64 + mi * 16 + g;
#pragma unroll
        for (int ni = 0; ni < 8; ++ni) {
            const int col = n0 + wn * 64 + ni * 8 + 2 * t;
#pragma unroll
            for (int h = 0; h < 2; ++h) {
                const int row = r0 + h * 8;
                float v0 = acc[mi][ni][h * 2 + 0];
                float v1 = acc[mi][ni][h * 2 + 1];
                if (MODE == 2) {
                    *reinterpret_cast<float2*>(&Cf[(size_t)row * ldc + col]) =
                        make_float2(v0, v1);
                } else {
                    // output n becomes a downstream k: store at permuted pos
                    const int pc0 = (col & ~31) | inv32(col & 31);
                    const int pc1 = ((col + 1) & ~31) | inv32((col + 1) & 31);
                    __half o0, o1;
                    if (MODE == 0) {
                        o0 = __float2half_rn(v0 + bvec[col]);
                        o1 = __float2half_rn(v1 + bvec[col + 1]);
                    } else {
                        o0 = (col     <= row - 4)
                                 ? __float2half_rn(__expf(v0 * 0.0625f - 6.0f))
                                 : __half(0.f);
                        o1 = (col + 1 <= row - 4)
                                 ? __float2half_rn(__expf(v1 * 0.0625f - 6.0f))
                                 : __half(0.f);
                    }
                    Ch[(size_t)row * ldc + pc0] = o0;
                    Ch[(size_t)row * ldc + pc1] = o1;
                }
            }
        }
    }
}

// ---------------------------------------------------------------------------
// K3: per row of g_s (permuted positions, fp16): l = sum p' (perm-invariant);
// combined[x] = 0.7*decay[orig(x)] + 0.3*p'[x]/l  (l==0 -> uniform 1/T).
// Stored fp16 in place (A operand of the final GEMM).
// ---------------------------------------------------------------------------
__global__ __launch_bounds__(256)
void k_combine(const float* __restrict__ decay) {
    __shared__ float red[256];
    const int r  = blockIdx.x;
    const int bz = r >> 12;
    const int i  = r & (kT - 1);
    __half*      srow = g_s   + (size_t)bz * kT * kT + (size_t)i * kT;
    const float* drow = decay + (size_t)bz * kT * kT + (size_t)i * kT;
    const int tid = threadIdx.x;

    // pass 1: row sum (fp32)
    float lsum = 0.f;
#pragma unroll
    for (int it = 0; it < 2; ++it) {
        int x = (tid + it * 256) * 8;
        uint4 pv = *reinterpret_cast<const uint4*>(srow + x);
        const __half2* ph = reinterpret_cast<const __half2*>(&pv);
#pragma unroll
        for (int j = 0; j < 4; ++j) {
            float2 f = __half22float2(ph[j]);
            lsum += f.x + f.y;
        }
    }
    red[tid] = lsum;
    __syncthreads();
    for (int s = 128; s > 0; s >>= 1) {
        if (tid < s) red[tid] += red[tid + s];
        __syncthreads();
    }
    const float l    = red[0];
    const float invl = (l > 0.f) ? (0.3f / l) : 0.f;
    const float base = (l > 0.f) ? 0.f : (0.3f / (float)kT);

    // pass 2: combine. Positions x..x+7 are chunk ct of a 32-group:
    // orig cols = g32 + {2t,2t+1, 2t+8,2t+9, 2t+16,2t+17, 2t+24,2t+25}.
#pragma unroll
    for (int it = 0; it < 2; ++it) {
        int x = (tid + it * 256) * 8;
        int g32 = x & ~31;
        int ct  = (x & 31) >> 3;
        int j0  = g32 + 2 * ct;
        float2 d0 = *reinterpret_cast<const float2*>(drow + j0);
        float2 d1 = *reinterpret_cast<const float2*>(drow + j0 + 8);
        float2 d2 = *reinterpret_cast<const float2*>(drow + j0 + 16);
        float2 d3 = *reinterpret_cast<const float2*>(drow + j0 + 24);
        uint4 pv = *reinterpret_cast<const uint4*>(srow + x);
        const __half2* ph = reinterpret_cast<const __half2*>(&pv);
        float2 p0 = __half22float2(ph[0]);
        float2 p1 = __half22float2(ph[1]);
        float2 p2 = __half22float2(ph[2]);
        float2 p3 = __half22float2(ph[3]);
        uint4 ov;
        __half2* oh = reinterpret_cast<__half2*>(&ov);
        oh[0] = __floats2half2_rn(0.7f * d0.x + invl * p0.x + base,
                                  0.7f * d0.y + invl * p0.y + base);
        oh[1] = __floats2half2_rn(0.7f * d1.x + invl * p1.x + base,
                                  0.7f * d1.y + invl * p1.y + base);
        oh[2] = __floats2half2_rn(0.7f * d2.x + invl * p2.x + base,
                                  0.7f * d2.y + invl * p2.y + base);
        oh[3] = __floats2half2_rn(0.7f * d3.x + invl * p3.x + base,
                                  0.7f * d3.y + invl * p3.y + base);
        *reinterpret_cast<uint4*>(srow + x) = ov;
    }
}

// ---------------------------------------------------------------------------
// launch
// ---------------------------------------------------------------------------
extern "C" void kernel_launch(void* const* d_in, const int* in_sizes, int n_in,
                              void* d_out, int out_size) {
    (void)in_sizes; (void)n_in; (void)out_size;
    const float* hdc   = (const float*)d_in[0];
    const float* decay = (const float*)d_in[1];
    const float* Wq    = (const float*)d_in[2];
    const float* bq    = (const float*)d_in[3];
    const float* Wk    = (const float*)d_in[4];
    const float* bk    = (const float*)d_in[5];
    float* out = (float*)d_out;

    cudaFuncSetAttribute(k_gemm<0>, cudaFuncAttributeMaxDynamicSharedMemorySize, SMEM);
    cudaFuncSetAttribute(k_gemm<1>, cudaFuncAttributeMaxDynamicSharedMemorySize, SMEM);
    cudaFuncSetAttribute(k_gemm<2>, cudaFuncAttributeMaxDynamicSharedMemorySize, SMEM);

    k_toh<<<512, 256>>>(Wq, kBot * kD, 1);
    k_toh<<<512, 256>>>(Wk, kBot * kD, 2);
    k_prep_hdc<<<dim3(kD / 32, kT / 32, kB), dim3(32, 8)>>>(hdc);

    // projections: q/k[16384,256] = hdc @ W^T + b   (z = 0:q, 1:k)
    k_gemm<0><<<dim3(kBot / TN, kM1 / TM, 2), 256, SMEM>>>(
        bq, const_cast<float*>(bk));

    // scores -> p' = exp(score - 6)
    k_gemm<1><<<dim3(kT / TN, kT / TM, kB), 256, SMEM>>>(nullptr, nullptr);

    k_combine<<<kM1, 256>>>(decay);

    // out = combined @ hdc
    k_gemm<2><<<dim3(kD / TN, kT / TM, kB), 256, SMEM>>>(nullptr, out);
}